// round 2
// baseline (speedup 1.0000x reference)
#include <cuda_runtime.h>
#include <math.h>

// reference(x) == softmax(max(x, axis=1), axis=-1)[:, None, :] * x
// (SSA with groups=1 + full-SVD reconstruction + anti-diagonal averaging is
//  the identity on the series xm, up to fp32 SVD roundoff ~1e-6 — well under
//  the 1e-3 rel-err gate.)
//
// x: [B=256, H=64, N=2048] fp32. One block per batch b:
//   phase 1: thread t owns columns (2t, 2t+1); running max over H in regs.
//            block-reduce row max M, then exp-sum S (two butterflies).
//   phase 2: re-read x (L2/DRAM), scale by gate (still in registers), store.
//
// __launch_bounds__(1024, 2): 2 blocks/SM -> all 256 blocks co-resident on
// 128 SMs (single wave, no tail), reductions of one block hidden by the
// other block's memory phase.

#define BATCH 256
#define HEADS 64
#define NCOLS 2048
#define NTHREADS 1024  // = NCOLS/2

__global__ __launch_bounds__(NTHREADS, 2)
void ssa_gate_kernel(const float* __restrict__ x, float* __restrict__ out) {
    const int b = blockIdx.x;
    const int t = threadIdx.x;

    const float2* __restrict__ xv =
        (const float2*)(x + (size_t)b * HEADS * NCOLS);
    float2* __restrict__ ov =
        (float2*)(out + (size_t)b * HEADS * NCOLS);

    __shared__ float sredA[32];
    __shared__ float sredB[32];

    // ---- phase 1: per-column max over heads (coalesced, high MLP) ----
    float mx = -INFINITY, my = -INFINITY;
    #pragma unroll 8
    for (int h = 0; h < HEADS; h++) {
        float2 v = xv[h * (NCOLS / 2) + t];
        mx = fmaxf(mx, v.x);
        my = fmaxf(my, v.y);
    }

    // ---- block max ----
    float m = fmaxf(mx, my);
    #pragma unroll
    for (int o = 16; o > 0; o >>= 1)
        m = fmaxf(m, __shfl_xor_sync(0xffffffffu, m, o));
    if ((t & 31) == 0) sredA[t >> 5] = m;
    __syncthreads();
    if (t < 32) {
        float v = sredA[t];
        #pragma unroll
        for (int o = 16; o > 0; o >>= 1)
            v = fmaxf(v, __shfl_xor_sync(0xffffffffu, v, o));
        sredA[t] = v;
    }
    __syncthreads();
    const float M = sredA[0];

    // ---- block exp-sum ----
    const float ex = __expf(mx - M);
    const float ey = __expf(my - M);
    float s = ex + ey;
    #pragma unroll
    for (int o = 16; o > 0; o >>= 1)
        s += __shfl_xor_sync(0xffffffffu, s, o);
    if ((t & 31) == 0) sredB[t >> 5] = s;
    __syncthreads();
    if (t < 32) {
        float v = sredB[t];
        #pragma unroll
        for (int o = 16; o > 0; o >>= 1)
            v += __shfl_xor_sync(0xffffffffu, v, o);
        sredB[t] = v;
    }
    __syncthreads();
    const float inv = 1.0f / sredB[0];

    const float gx = ex * inv;
    const float gy = ey * inv;

    // ---- phase 2: scale + store. Loads are last-use (__ldcs evict-first),
    //      stores never re-read (__stcs streaming) -> protect L2 for
    //      other blocks' phase-1 data. ----
    #pragma unroll 8
    for (int h = 0; h < HEADS; h++) {
        float2 v = __ldcs(&xv[h * (NCOLS / 2) + t]);
        v.x *= gx;
        v.y *= gy;
        __stcs(&ov[h * (NCOLS / 2) + t], v);
    }
}

extern "C" void kernel_launch(void* const* d_in, const int* in_sizes, int n_in,
                              void* d_out, int out_size) {
    const float* x = (const float*)d_in[0];
    float* out = (float*)d_out;
    ssa_gate_kernel<<<BATCH, NTHREADS>>>(x, out);
}